// round 8
// baseline (speedup 1.0000x reference)
#include <cuda_runtime.h>
#include <math.h>

#define NN 50000
#define GG 8
#define EE 400000
#define DD 512
#define HC 512
#define ETOT (EE + NN)

// ---------------- static scratch (no allocations allowed) ----------------
__device__ float d_h[NN * HC];      // h = x @ W
__device__ float d_hconv[NN * HC];  // GAT output (+ b_conv)
__device__ float d_as[NN];
__device__ float d_ad[NN];
__device__ float d_gate[NN];
__device__ float d_g[NN];
__device__ int   d_deg[NN];
__device__ int   d_offsets[NN + 1];
__device__ int   d_pos[NN];
__device__ int   d_csr_src[ETOT];
__device__ unsigned d_gmax[GG];
__device__ float d_gsum[GG];
__device__ float d_P[GG * HC];       // sum_i g_i * hconv_i
__device__ float d_pooled[GG * HC];  // P @ Wn + bn
__device__ float d_t1[GG * HC];      // relu(pooled @ W1 + b1)
__device__ int   d_ei64;             // 1 if edge_index is int64, 0 if int32
__device__ int   d_bat64;            // 1 if batch is int64, 0 if int32

// ---- index loading that works for either int32 or int64 harness delivery ----
__device__ __forceinline__ int load_idx(const void* p, int i, int is64) {
    if (is64) return (int)((const long long*)p)[i];
    return ((const int*)p)[i];
}

// ordered-float encoding for atomicMax on floats
__device__ __forceinline__ unsigned fenc(float f) {
    unsigned u = __float_as_uint(f);
    return (u & 0x80000000u) ? ~u : (u | 0x80000000u);
}
__device__ __forceinline__ float fdec(unsigned u) {
    u = (u & 0x80000000u) ? (u & 0x7fffffffu) : ~u;
    return __uint_as_float(u);
}

// ---------------- dtype detect + init ----------------
// int64 values here are small non-negative (< 2^31): their high 32-bit words
// are all zero. For int32 delivery the odd 32-bit slots hold independent
// values (random node ids / sorted batch ids spanning 0..G-1 over 64 slots),
// which are not all zero. 64 samples -> misdetection probability ~0.
__global__ void detect_kernel(const void* ei_raw, const void* bat_raw) {
    if (threadIdx.x == 0 && blockIdx.x == 0) {
        const int* p = (const int*)ei_raw;
        int is64 = 1;
        for (int i = 0; i < 64; i++)
            if (p[2 * i + 1] != 0) { is64 = 0; break; }
        d_ei64 = is64;
    }
    if (threadIdx.x == 1 && blockIdx.x == 0) {
        // sample spread-out positions: batch is sorted, so late entries are >0
        const int* q = (const int*)bat_raw;
        int is64 = 1;
        for (int i = 0; i < 64; i++) {
            int pos = i * (NN / 64) + (NN / 128);
            if (q[2 * pos + 1] != 0) { is64 = 0; break; }
        }
        d_bat64 = is64;
    }
}

__global__ void init_kernel() {
    int i = blockIdx.x * blockDim.x + threadIdx.x;
    if (i < NN) d_deg[i] = 1;  // self-loop counts as 1
    if (i < GG) { d_gmax[i] = 0x007FFFFFu; d_gsum[i] = 0.0f; }
    if (i < GG * HC) d_P[i] = 0.0f;
    if (i == 0) d_offsets[0] = 0;
}

// ---------------- SGEMM: d_h[M,512] = A[M,512] @ B[512,512] ----------------
#define BM 128
#define BN 128
#define BK 16
#define TM 8
#define TN 8
__global__ __launch_bounds__(256) void sgemm_kernel(const float* __restrict__ A,
                                                    const float* __restrict__ B, int M) {
    __shared__ float As[BK][BM];
    __shared__ float Bs[BK][BN];
    const int bn = blockIdx.x, bm = blockIdx.y;
    const int tid = threadIdx.x;
    const int arow = tid >> 2;          // 0..63, two iters (+64)
    const int acol4 = tid & 3;          // float4 along K
    const int brow = tid >> 5;          // 0..7, two iters (+8)
    const int bcol4 = tid & 31;         // float4 along N
    const int tr = (tid >> 4) * TM;
    const int tc = (tid & 15) * TN;
    const int gr0 = bm * BM;

    float acc[TM][TN];
#pragma unroll
    for (int i = 0; i < TM; i++)
#pragma unroll
        for (int j = 0; j < TN; j++) acc[i][j] = 0.0f;

    for (int k0 = 0; k0 < DD; k0 += BK) {
        // load A tile (with M guard), store transposed
#pragma unroll
        for (int it = 0; it < 2; it++) {
            int r = arow + it * 64;
            int gr = gr0 + r;
            float4 v = make_float4(0.f, 0.f, 0.f, 0.f);
            if (gr < M) v = *(const float4*)(A + (size_t)gr * DD + k0 + acol4 * 4);
            As[acol4 * 4 + 0][r] = v.x;
            As[acol4 * 4 + 1][r] = v.y;
            As[acol4 * 4 + 2][r] = v.z;
            As[acol4 * 4 + 3][r] = v.w;
        }
        // load B tile
#pragma unroll
        for (int it = 0; it < 2; it++) {
            int kr = brow + it * 8;
            float4 v = *(const float4*)(B + (size_t)(k0 + kr) * HC + bn * BN + bcol4 * 4);
            *((float4*)&Bs[kr][0] + bcol4) = v;
        }
        __syncthreads();
#pragma unroll
        for (int k = 0; k < BK; k++) {
            float ra[TM], rb[TN];
            *(float4*)&ra[0] = *(const float4*)&As[k][tr];
            *(float4*)&ra[4] = *(const float4*)&As[k][tr + 4];
            *(float4*)&rb[0] = *(const float4*)&Bs[k][tc];
            *(float4*)&rb[4] = *(const float4*)&Bs[k][tc + 4];
#pragma unroll
            for (int i = 0; i < TM; i++)
#pragma unroll
                for (int j = 0; j < TN; j++) acc[i][j] += ra[i] * rb[j];
        }
        __syncthreads();
    }
#pragma unroll
    for (int i = 0; i < TM; i++) {
        int gr = gr0 + tr + i;
        if (gr < M) {
            float4* c4 = (float4*)(d_h + (size_t)gr * HC + bn * BN + tc);
            c4[0] = make_float4(acc[i][0], acc[i][1], acc[i][2], acc[i][3]);
            c4[1] = make_float4(acc[i][4], acc[i][5], acc[i][6], acc[i][7]);
        }
    }
}

// ---------------- a_s, a_d GEMV: one warp per row ----------------
__global__ void gemv_attn_kernel(const float* __restrict__ att_s,
                                 const float* __restrict__ att_d) {
    int warp = (blockIdx.x * blockDim.x + threadIdx.x) >> 5;
    int lane = threadIdx.x & 31;
    if (warp >= NN) return;
    const float4* hr = (const float4*)(d_h + (size_t)warp * HC);
    const float4* s4 = (const float4*)att_s;
    const float4* t4 = (const float4*)att_d;
    float ss = 0.f, dd = 0.f;
#pragma unroll
    for (int i = 0; i < 4; i++) {
        int idx = lane + i * 32;
        float4 hv = hr[idx];
        float4 a = s4[idx];
        float4 b = t4[idx];
        ss += hv.x * a.x + hv.y * a.y + hv.z * a.z + hv.w * a.w;
        dd += hv.x * b.x + hv.y * b.y + hv.z * b.z + hv.w * b.w;
    }
#pragma unroll
    for (int o = 16; o; o >>= 1) {
        ss += __shfl_xor_sync(0xffffffffu, ss, o);
        dd += __shfl_xor_sync(0xffffffffu, dd, o);
    }
    if (lane == 0) { d_as[warp] = ss; d_ad[warp] = dd; }
}

// ---------------- CSR build ----------------
__global__ void count_deg_kernel(const void* __restrict__ ei) {
    int e = blockIdx.x * blockDim.x + threadIdx.x;
    if (e >= EE) return;
    int dst = load_idx(ei, EE + e, d_ei64);
    atomicAdd(&d_deg[dst], 1);
}

__global__ __launch_bounds__(1024) void scan_kernel() {
    __shared__ int sh[1024];
    __shared__ int carry;
    int tid = threadIdx.x;
    if (tid == 0) carry = 0;
    __syncthreads();
    for (int base = 0; base < NN; base += 1024) {
        int i = base + tid;
        int v = (i < NN) ? d_deg[i] : 0;
        sh[tid] = v;
        __syncthreads();
        for (int off = 1; off < 1024; off <<= 1) {
            int t = (tid >= off) ? sh[tid - off] : 0;
            __syncthreads();
            sh[tid] += t;
            __syncthreads();
        }
        int inc = sh[tid] + carry;
        if (i < NN) { d_offsets[i + 1] = inc; d_pos[i] = inc - v; }
        __syncthreads();
        if (tid == 1023) carry = inc;
        __syncthreads();
    }
}

__global__ void fill_self_kernel() {
    int i = blockIdx.x * blockDim.x + threadIdx.x;
    if (i < NN) d_csr_src[d_offsets[i + 1] - 1] = i;  // self-loop in last slot
}

__global__ void fill_edges_kernel(const void* __restrict__ ei) {
    int e = blockIdx.x * blockDim.x + threadIdx.x;
    if (e >= EE) return;
    int is64 = d_ei64;
    int dst = load_idx(ei, EE + e, is64);
    int src = load_idx(ei, e, is64);
    int slot = atomicAdd(&d_pos[dst], 1);
    d_csr_src[slot] = src;
}

// ---------------- per-node softmax + weighted gather (warp/node) ----------
// also fuses: + b_conv and gate = hconv . Wg + bg
__global__ __launch_bounds__(256) void gather_kernel(const float* __restrict__ b_conv,
                                                     const float* __restrict__ Wg,
                                                     const float* __restrict__ bg) {
    int warp = (blockIdx.x * blockDim.x + threadIdx.x) >> 5;
    int lane = threadIdx.x & 31;
    if (warp >= NN) return;
    const int n = warp;
    const int beg = d_offsets[n];
    const int end = d_offsets[n + 1];
    const float adn = d_ad[n];

    // pass 1: max
    float m = -INFINITY;
    for (int j = beg + lane; j < end; j += 32) {
        int s = d_csr_src[j];
        float e = d_as[s] + adn;
        e = (e > 0.f) ? e : 0.2f * e;
        m = fmaxf(m, e);
    }
#pragma unroll
    for (int o = 16; o; o >>= 1) m = fmaxf(m, __shfl_xor_sync(0xffffffffu, m, o));
    if (!isfinite(m)) m = 0.f;

    // pass 2: sum(exp)
    float sum = 0.f;
    for (int j = beg + lane; j < end; j += 32) {
        int s = d_csr_src[j];
        float e = d_as[s] + adn;
        e = (e > 0.f) ? e : 0.2f * e;
        sum += expf(e - m);
    }
#pragma unroll
    for (int o = 16; o; o >>= 1) sum += __shfl_xor_sync(0xffffffffu, sum, o);
    const float inv = 1.0f / (sum + 1e-16f);

    // pass 3: weighted gather (each lane owns 4 float4s, stride-32)
    const float4* bc4 = (const float4*)b_conv;
    float4 a0 = bc4[lane];
    float4 a1 = bc4[lane + 32];
    float4 a2 = bc4[lane + 64];
    float4 a3 = bc4[lane + 96];
    for (int j = beg; j < end; j++) {
        int s = d_csr_src[j];
        float e = d_as[s] + adn;
        e = (e > 0.f) ? e : 0.2f * e;
        float alpha = expf(e - m) * inv;
        const float4* hr = (const float4*)(d_h + (size_t)s * HC);
        float4 v;
        v = hr[lane];      a0.x += alpha * v.x; a0.y += alpha * v.y; a0.z += alpha * v.z; a0.w += alpha * v.w;
        v = hr[lane + 32]; a1.x += alpha * v.x; a1.y += alpha * v.y; a1.z += alpha * v.z; a1.w += alpha * v.w;
        v = hr[lane + 64]; a2.x += alpha * v.x; a2.y += alpha * v.y; a2.z += alpha * v.z; a2.w += alpha * v.w;
        v = hr[lane + 96]; a3.x += alpha * v.x; a3.y += alpha * v.y; a3.z += alpha * v.z; a3.w += alpha * v.w;
    }
    float4* out4 = (float4*)(d_hconv + (size_t)n * HC);
    out4[lane] = a0; out4[lane + 32] = a1; out4[lane + 64] = a2; out4[lane + 96] = a3;

    // fused gate GEMV
    const float4* wg4 = (const float4*)Wg;
    float gd = 0.f;
    float4 w;
    w = wg4[lane];      gd += a0.x * w.x + a0.y * w.y + a0.z * w.z + a0.w * w.w;
    w = wg4[lane + 32]; gd += a1.x * w.x + a1.y * w.y + a1.z * w.z + a1.w * w.w;
    w = wg4[lane + 64]; gd += a2.x * w.x + a2.y * w.y + a2.z * w.z + a2.w * w.w;
    w = wg4[lane + 96]; gd += a3.x * w.x + a3.y * w.y + a3.z * w.z + a3.w * w.w;
#pragma unroll
    for (int o = 16; o; o >>= 1) gd += __shfl_xor_sync(0xffffffffu, gd, o);
    if (lane == 0) d_gate[n] = gd + bg[0];
}

// ---------------- batch softmax (G=8) ----------------
__global__ void batch_max_kernel(const void* __restrict__ batch) {
    __shared__ unsigned sm[GG];
    if (threadIdx.x < GG) sm[threadIdx.x] = 0x007FFFFFu;  // enc(-inf)
    __syncthreads();
    int is64 = d_bat64;
    for (int i = blockIdx.x * blockDim.x + threadIdx.x; i < NN; i += gridDim.x * blockDim.x) {
        int b = load_idx(batch, i, is64);
        atomicMax(&sm[b], fenc(d_gate[i]));
    }
    __syncthreads();
    if (threadIdx.x < GG) atomicMax(&d_gmax[threadIdx.x], sm[threadIdx.x]);
}

__global__ void batch_sum_kernel(const void* __restrict__ batch) {
    __shared__ float ss[GG];
    __shared__ float mm[GG];
    if (threadIdx.x < GG) {
        ss[threadIdx.x] = 0.f;
        float mv = fdec(d_gmax[threadIdx.x]);
        mm[threadIdx.x] = isfinite(mv) ? mv : 0.f;
    }
    __syncthreads();
    int is64 = d_bat64;
    for (int i = blockIdx.x * blockDim.x + threadIdx.x; i < NN; i += gridDim.x * blockDim.x) {
        int b = load_idx(batch, i, is64);
        atomicAdd(&ss[b], expf(d_gate[i] - mm[b]));
    }
    __syncthreads();
    if (threadIdx.x < GG) atomicAdd(&d_gsum[threadIdx.x], ss[threadIdx.x]);
}

__global__ void g_kernel(const void* __restrict__ batch, float* __restrict__ out,
                         int out_size) {
    int i = blockIdx.x * blockDim.x + threadIdx.x;
    if (i >= NN) return;
    int b = load_idx(batch, i, d_bat64);
    float mv = fdec(d_gmax[b]);
    if (!isfinite(mv)) mv = 0.f;
    float g = expf(d_gate[i] - mv) / (d_gsum[b] + 1e-16f);
    d_g[i] = g;
    if (out_size >= GG + NN) out[GG + i] = g;
}

// ---------------- pooled pre-GEMM: P[b,c] = sum_i g_i * hconv[i,c] ----------
__global__ __launch_bounds__(128) void pool_P_kernel(const void* __restrict__ batch) {
    const int col = blockIdx.x * 128 + threadIdx.x;
    const int r0 = blockIdx.y * 128;
    const int rend = min(r0 + 128, NN);
    const int is64 = d_bat64;
    float acc = 0.f;
    int cur = load_idx(batch, r0, is64);
    for (int r = r0; r < rend; r++) {
        int b = load_idx(batch, r, is64);
        if (b != cur) {
            atomicAdd(&d_P[cur * HC + col], acc);
            acc = 0.f;
            cur = b;
        }
        acc += d_g[r] * d_hconv[(size_t)r * HC + col];
    }
    atomicAdd(&d_P[cur * HC + col], acc);
}

// ---------------- small [G,HC] @ [HC,HC] matmuls: warp per output ----------
// which = 0: d_pooled = d_P @ Wn + bn
// which = 1: d_t1 = relu(d_pooled @ W1 + b1)
__global__ void mm_small_kernel(const float* __restrict__ Bm, const float* __restrict__ bias,
                                int which) {
    int warp = (blockIdx.x * blockDim.x + threadIdx.x) >> 5;
    int lane = threadIdx.x & 31;
    if (warp >= GG * HC) return;
    int gi = warp >> 9;   // /HC
    int c = warp & 511;   // %HC
    const float* A = (which == 0) ? d_P : d_pooled;
    float s = 0.f;
    for (int k = lane; k < HC; k += 32) s += A[gi * HC + k] * Bm[(size_t)k * HC + c];
#pragma unroll
    for (int o = 16; o; o >>= 1) s += __shfl_xor_sync(0xffffffffu, s, o);
    if (lane == 0) {
        float v = s + bias[c];
        if (which == 1) v = fmaxf(v, 0.f);
        if (which == 0) d_pooled[gi * HC + c] = v;
        else            d_t1[gi * HC + c] = v;
    }
}

// ---------------- final: out[g] = sigmoid(t1[g] . W2 + b2) ----------------
__global__ void out_kernel(const float* __restrict__ W2, const float* __restrict__ b2,
                           float* __restrict__ out) {
    int warp = threadIdx.x >> 5;
    int lane = threadIdx.x & 31;
    if (warp >= GG) return;
    float s = 0.f;
    for (int k = lane; k < HC; k += 32) s += d_t1[warp * HC + k] * W2[k];
#pragma unroll
    for (int o = 16; o; o >>= 1) s += __shfl_xor_sync(0xffffffffu, s, o);
    if (lane == 0) {
        float v = s + b2[0];
        out[warp] = 1.0f / (1.0f + expf(-v));
    }
}

// ---------------- launch ----------------
extern "C" void kernel_launch(void* const* d_in, const int* in_sizes, int n_in,
                              void* d_out, int out_size) {
    const float* x       = (const float*)d_in[0];
    const void*  ei      = d_in[1];  // int32 or int64, detected on device
    const void*  bat     = d_in[2];  // int32 or int64, detected on device
    const float* W       = (const float*)d_in[3];
    const float* att_src = (const float*)d_in[4];
    const float* att_dst = (const float*)d_in[5];
    const float* b_conv  = (const float*)d_in[6];
    const float* Wg      = (const float*)d_in[7];
    const float* bg      = (const float*)d_in[8];
    const float* Wn      = (const float*)d_in[9];
    const float* bn      = (const float*)d_in[10];
    const float* W1      = (const float*)d_in[11];
    const float* b1      = (const float*)d_in[12];
    const float* W2      = (const float*)d_in[13];
    const float* b2      = (const float*)d_in[14];
    float* out = (float*)d_out;

    detect_kernel<<<1, 32>>>(ei, bat);
    init_kernel<<<(NN + 255) / 256, 256>>>();

    // h = x @ W
    dim3 gg(HC / BN, (NN + BM - 1) / BM);
    sgemm_kernel<<<gg, 256>>>(x, W, NN);

    gemv_attn_kernel<<<(NN * 32 + 255) / 256, 256>>>(att_src, att_dst);

    count_deg_kernel<<<(EE + 255) / 256, 256>>>(ei);
    scan_kernel<<<1, 1024>>>();
    fill_self_kernel<<<(NN + 255) / 256, 256>>>();
    fill_edges_kernel<<<(EE + 255) / 256, 256>>>(ei);

    gather_kernel<<<(NN * 32 + 255) / 256, 256>>>(b_conv, Wg, bg);

    batch_max_kernel<<<200, 256>>>(bat);
    batch_sum_kernel<<<200, 256>>>(bat);
    g_kernel<<<(NN + 255) / 256, 256>>>(bat, out, out_size);

    dim3 pg(HC / 128, (NN + 127) / 128);
    pool_P_kernel<<<pg, 128>>>(bat);

    // pooled = P @ Wn + bn ; t1 = relu(pooled @ W1 + b1) ; out = sigmoid(t1 @ W2 + b2)
    mm_small_kernel<<<(GG * HC * 32 + 255) / 256, 256>>>(Wn, bn, 0);
    mm_small_kernel<<<(GG * HC * 32 + 255) / 256, 256>>>(W1, b1, 1);
    out_kernel<<<1, 256>>>(W2, b2, out);
}

// round 16
// speedup vs baseline: 1.4490x; 1.4490x over previous
#include <cuda_runtime.h>
#include <cuda_bf16.h>
#include <stdint.h>
#include <math.h>

#define NN 50000
#define GG 8
#define EE 400000
#define DD 512
#define HC 512
#define ETOT (EE + NN)

// ---------------- static scratch (no allocations allowed) ----------------
__device__ float d_h[NN * HC];      // h = x @ W
__device__ float d_hconv[NN * HC];  // GAT output (+ b_conv)
__device__ __nv_bfloat16 d_xhi[NN * DD];
__device__ __nv_bfloat16 d_xlo[NN * DD];
__device__ __nv_bfloat16 d_whit[DD * HC];  // W^T hi  [n][k]
__device__ __nv_bfloat16 d_wlot[DD * HC];  // W^T lo  [n][k]
__device__ float d_as[NN];
__device__ float d_ad[NN];
__device__ float d_gate[NN];
__device__ float d_g[NN];
__device__ int   d_deg[NN];
__device__ int   d_offsets[NN + 1];
__device__ int   d_pos[NN];
__device__ int   d_csr_src[ETOT];
__device__ unsigned d_gmax[GG];
__device__ float d_gsum[GG];
__device__ float d_P[GG * HC];
__device__ float d_pooled[GG * HC];
__device__ float d_t1[GG * HC];
__device__ int   d_ei64;
__device__ int   d_bat64;

// ---- index loading that works for either int32 or int64 harness delivery ----
__device__ __forceinline__ int load_idx(const void* p, int i, int is64) {
    if (is64) return (int)((const long long*)p)[i];
    return ((const int*)p)[i];
}
__device__ __forceinline__ unsigned fenc(float f) {
    unsigned u = __float_as_uint(f);
    return (u & 0x80000000u) ? ~u : (u | 0x80000000u);
}
__device__ __forceinline__ float fdec(unsigned u) {
    u = (u & 0x80000000u) ? (u & 0x7fffffffu) : ~u;
    return __uint_as_float(u);
}

// ---------------- dtype detect + init ----------------
__global__ void detect_kernel(const void* ei_raw, const void* bat_raw) {
    if (threadIdx.x == 0 && blockIdx.x == 0) {
        const int* p = (const int*)ei_raw;
        int is64 = 1;
        for (int i = 0; i < 64; i++)
            if (p[2 * i + 1] != 0) { is64 = 0; break; }
        d_ei64 = is64;
    }
    if (threadIdx.x == 1 && blockIdx.x == 0) {
        const int* q = (const int*)bat_raw;
        int is64 = 1;
        for (int i = 0; i < 64; i++) {
            int pos = i * (NN / 64) + (NN / 128);
            if (q[2 * pos + 1] != 0) { is64 = 0; break; }
        }
        d_bat64 = is64;
    }
}

__global__ void init_kernel() {
    int i = blockIdx.x * blockDim.x + threadIdx.x;
    if (i < NN) d_deg[i] = 1;
    if (i < GG) { d_gmax[i] = 0x007FFFFFu; d_gsum[i] = 0.0f; }
    if (i < GG * HC) d_P[i] = 0.0f;
    if (i == 0) d_offsets[0] = 0;
}

// ---------------- split kernels (fp32 -> bf16 hi/lo) ----------------
__global__ void split_x_kernel(const float* __restrict__ x) {
    int i = blockIdx.x * blockDim.x + threadIdx.x;
    const int total = NN * DD / 4;
    if (i >= total) return;
    float4 v = ((const float4*)x)[i];
    __nv_bfloat16 h0 = __float2bfloat16(v.x), h1 = __float2bfloat16(v.y);
    __nv_bfloat16 h2 = __float2bfloat16(v.z), h3 = __float2bfloat16(v.w);
    float l0 = v.x - __bfloat162float(h0), l1 = v.y - __bfloat162float(h1);
    float l2 = v.z - __bfloat162float(h2), l3 = v.w - __bfloat162float(h3);
    uint2 ph, pl;
    ph.x = ((uint32_t)__bfloat16_as_ushort(h1) << 16) | __bfloat16_as_ushort(h0);
    ph.y = ((uint32_t)__bfloat16_as_ushort(h3) << 16) | __bfloat16_as_ushort(h2);
    __nv_bfloat16 g0 = __float2bfloat16(l0), g1 = __float2bfloat16(l1);
    __nv_bfloat16 g2 = __float2bfloat16(l2), g3 = __float2bfloat16(l3);
    pl.x = ((uint32_t)__bfloat16_as_ushort(g1) << 16) | __bfloat16_as_ushort(g0);
    pl.y = ((uint32_t)__bfloat16_as_ushort(g3) << 16) | __bfloat16_as_ushort(g2);
    ((uint2*)d_xhi)[i] = ph;
    ((uint2*)d_xlo)[i] = pl;
}

__global__ void split_w_kernel(const float* __restrict__ W) {
    int idx = blockIdx.x * blockDim.x + threadIdx.x;  // n*512 + k
    if (idx >= DD * HC) return;
    int n = idx >> 9, k = idx & 511;
    float v = W[k * HC + n];  // transpose: W[k][n] -> Wt[n][k]
    __nv_bfloat16 hi = __float2bfloat16(v);
    float lo = v - __bfloat162float(hi);
    d_whit[idx] = hi;
    d_wlot[idx] = __float2bfloat16(lo);
}

// ---------------- HMMA bf16-split GEMM: d_h = x @ W ----------------
// mma.sync.m16n8k16 (sm_80+ path, works on compute_103 non-'a' target).
// CTA tile 128x128, 8 warps (warp tile 32x64), K chunks of 32,
// double-buffered SMEM, 3 MMAs per fragment (hi*hi + hi*lo + lo*hi).
#define KC 32
#define PAB 40                    // smem row pitch in bf16 (80 bytes) -> conflict-free
#define TILE_SB (128 * PAB * 2)   // 10240 bytes per tile
#define BUF_SB (4 * TILE_SB)      // Ah, Al, Bh, Bl
#define GEMM_SMEM (2 * BUF_SB)    // 81920 bytes

__device__ __forceinline__ void mma16816(float* c, const uint32_t* a, const uint32_t* b) {
    asm volatile(
        "mma.sync.aligned.m16n8k16.row.col.f32.bf16.bf16.f32 "
        "{%0,%1,%2,%3}, {%4,%5,%6,%7}, {%8,%9}, {%0,%1,%2,%3};"
        : "+f"(c[0]), "+f"(c[1]), "+f"(c[2]), "+f"(c[3])
        : "r"(a[0]), "r"(a[1]), "r"(a[2]), "r"(a[3]), "r"(b[0]), "r"(b[1]));
}

__global__ __launch_bounds__(256) void gemm_mma_kernel() {
    extern __shared__ char smem[];
    const int tid = threadIdx.x, wid = tid >> 5, lane = tid & 31;
    const int g = lane >> 2, tg = lane & 3;
    const int warp_m = wid & 3, warp_n = wid >> 2;   // 4 x 2 warps
    const int bn = blockIdx.x, bm = blockIdx.y;
    const int m0 = bm * 128;

    float acc[2][8][4];
#pragma unroll
    for (int a = 0; a < 2; a++)
#pragma unroll
        for (int b = 0; b < 8; b++)
#pragma unroll
            for (int c = 0; c < 4; c++) acc[a][b][c] = 0.0f;

    // prefetch registers: [Ah x2][Al x2][Bh x2][Bl x2]
    uint4 pf[8];
    const int row = tid >> 2;                // 0..63 (+64 for second iter)
    const int c16 = tid & 3;                 // 16B chunk within 32-bf16 row

    // ---- load chunk c into pf ----
    auto load_chunk = [&](int c) {
#pragma unroll
        for (int it = 0; it < 2; it++) {
            int r = row + it * 64;
            int k0g = c * KC + c16 * 8;
            int gr = m0 + r;
            uint4 vh = make_uint4(0, 0, 0, 0), vl = make_uint4(0, 0, 0, 0);
            if (gr < NN) {
                vh = *(const uint4*)(d_xhi + (size_t)gr * DD + k0g);
                vl = *(const uint4*)(d_xlo + (size_t)gr * DD + k0g);
            }
            pf[it] = vh;
            pf[2 + it] = vl;
            int n = bn * 128 + r;
            pf[4 + it] = *(const uint4*)(d_whit + (size_t)n * DD + k0g);
            pf[6 + it] = *(const uint4*)(d_wlot + (size_t)n * DD + k0g);
        }
    };
    // ---- store pf into smem buffer b ----
    auto store_chunk = [&](int b) {
        char* base = smem + b * BUF_SB;
#pragma unroll
        for (int it = 0; it < 2; it++) {
            int r = row + it * 64;
            int off = r * (PAB * 2) + c16 * 16;
            *(uint4*)(base + off) = pf[it];
            *(uint4*)(base + TILE_SB + off) = pf[2 + it];
            *(uint4*)(base + 2 * TILE_SB + off) = pf[4 + it];
            *(uint4*)(base + 3 * TILE_SB + off) = pf[6 + it];
        }
    };

    load_chunk(0);
    store_chunk(0);
    __syncthreads();

    const int NCHUNK = DD / KC;  // 16
    for (int c = 0; c < NCHUNK; c++) {
        if (c + 1 < NCHUNK) load_chunk(c + 1);

        const char* base = smem + (c & 1) * BUF_SB;
        const char* sAh = base;
        const char* sAl = base + TILE_SB;
        const char* sBh = base + 2 * TILE_SB;
        const char* sBl = base + 3 * TILE_SB;

#pragma unroll
        for (int kk = 0; kk < 2; kk++) {
            const int kb = kk * 32 + tg * 4;  // byte offset of this lane's k pair
            uint32_t Ah[2][4], Al[2][4];
#pragma unroll
            for (int tm = 0; tm < 2; tm++) {
                int rb = (warp_m * 32 + tm * 16 + g) * (PAB * 2) + kb;
                Ah[tm][0] = *(const uint32_t*)(sAh + rb);
                Ah[tm][1] = *(const uint32_t*)(sAh + rb + 8 * PAB * 2);
                Ah[tm][2] = *(const uint32_t*)(sAh + rb + 16);
                Ah[tm][3] = *(const uint32_t*)(sAh + rb + 8 * PAB * 2 + 16);
                Al[tm][0] = *(const uint32_t*)(sAl + rb);
                Al[tm][1] = *(const uint32_t*)(sAl + rb + 8 * PAB * 2);
                Al[tm][2] = *(const uint32_t*)(sAl + rb + 16);
                Al[tm][3] = *(const uint32_t*)(sAl + rb + 8 * PAB * 2 + 16);
            }
#pragma unroll
            for (int tn = 0; tn < 8; tn++) {
                int nb = (warp_n * 64 + tn * 8 + g) * (PAB * 2) + kb;
                uint32_t Bh[2], Bl[2];
                Bh[0] = *(const uint32_t*)(sBh + nb);
                Bh[1] = *(const uint32_t*)(sBh + nb + 16);
                Bl[0] = *(const uint32_t*)(sBl + nb);
                Bl[1] = *(const uint32_t*)(sBl + nb + 16);
#pragma unroll
                for (int tm = 0; tm < 2; tm++) {
                    mma16816(acc[tm][tn], Ah[tm], Bh);
                    mma16816(acc[tm][tn], Ah[tm], Bl);
                    mma16816(acc[tm][tn], Al[tm], Bh);
                }
            }
        }

        if (c + 1 < NCHUNK) store_chunk((c + 1) & 1);
        __syncthreads();
    }

    // epilogue: write fp32 accumulators to d_h
#pragma unroll
    for (int tm = 0; tm < 2; tm++) {
        int r0 = m0 + warp_m * 32 + tm * 16 + g;
#pragma unroll
        for (int tn = 0; tn < 8; tn++) {
            int col = bn * 128 + warp_n * 64 + tn * 8 + tg * 2;
            if (r0 < NN)
                *(float2*)(d_h + (size_t)r0 * HC + col) = make_float2(acc[tm][tn][0], acc[tm][tn][1]);
            if (r0 + 8 < NN)
                *(float2*)(d_h + (size_t)(r0 + 8) * HC + col) = make_float2(acc[tm][tn][2], acc[tm][tn][3]);
        }
    }
}

// ---------------- a_s, a_d GEMV: one warp per row ----------------
__global__ void gemv_attn_kernel(const float* __restrict__ att_s,
                                 const float* __restrict__ att_d) {
    int warp = (blockIdx.x * blockDim.x + threadIdx.x) >> 5;
    int lane = threadIdx.x & 31;
    if (warp >= NN) return;
    const float4* hr = (const float4*)(d_h + (size_t)warp * HC);
    const float4* s4 = (const float4*)att_s;
    const float4* t4 = (const float4*)att_d;
    float ss = 0.f, dd = 0.f;
#pragma unroll
    for (int i = 0; i < 4; i++) {
        int idx = lane + i * 32;
        float4 hv = hr[idx];
        float4 a = s4[idx];
        float4 b = t4[idx];
        ss += hv.x * a.x + hv.y * a.y + hv.z * a.z + hv.w * a.w;
        dd += hv.x * b.x + hv.y * b.y + hv.z * b.z + hv.w * b.w;
    }
#pragma unroll
    for (int o = 16; o; o >>= 1) {
        ss += __shfl_xor_sync(0xffffffffu, ss, o);
        dd += __shfl_xor_sync(0xffffffffu, dd, o);
    }
    if (lane == 0) { d_as[warp] = ss; d_ad[warp] = dd; }
}

// ---------------- CSR build ----------------
__global__ void count_deg_kernel(const void* __restrict__ ei) {
    int e = blockIdx.x * blockDim.x + threadIdx.x;
    if (e >= EE) return;
    int dst = load_idx(ei, EE + e, d_ei64);
    atomicAdd(&d_deg[dst], 1);
}

__global__ __launch_bounds__(1024) void scan_kernel() {
    __shared__ int sh[1024];
    __shared__ int carry;
    int tid = threadIdx.x;
    if (tid == 0) carry = 0;
    __syncthreads();
    for (int base = 0; base < NN; base += 1024) {
        int i = base + tid;
        int v = (i < NN) ? d_deg[i] : 0;
        sh[tid] = v;
        __syncthreads();
        for (int off = 1; off < 1024; off <<= 1) {
            int t = (tid >= off) ? sh[tid - off] : 0;
            __syncthreads();
            sh[tid] += t;
            __syncthreads();
        }
        int inc = sh[tid] + carry;
        if (i < NN) { d_offsets[i + 1] = inc; d_pos[i] = inc - v; }
        __syncthreads();
        if (tid == 1023) carry = inc;
        __syncthreads();
    }
}

__global__ void fill_self_kernel() {
    int i = blockIdx.x * blockDim.x + threadIdx.x;
    if (i < NN) d_csr_src[d_offsets[i + 1] - 1] = i;
}

__global__ void fill_edges_kernel(const void* __restrict__ ei) {
    int e = blockIdx.x * blockDim.x + threadIdx.x;
    if (e >= EE) return;
    int is64 = d_ei64;
    int dst = load_idx(ei, EE + e, is64);
    int src = load_idx(ei, e, is64);
    int slot = atomicAdd(&d_pos[dst], 1);
    d_csr_src[slot] = src;
}

// ---------------- per-node softmax + weighted gather (warp/node) ----------
__global__ __launch_bounds__(256) void gather_kernel(const float* __restrict__ b_conv,
                                                     const float* __restrict__ Wg,
                                                     const float* __restrict__ bg) {
    int warp = (blockIdx.x * blockDim.x + threadIdx.x) >> 5;
    int lane = threadIdx.x & 31;
    if (warp >= NN) return;
    const int n = warp;
    const int beg = d_offsets[n];
    const int end = d_offsets[n + 1];
    const float adn = d_ad[n];

    float m = -INFINITY;
    for (int j = beg + lane; j < end; j += 32) {
        int s = d_csr_src[j];
        float e = d_as[s] + adn;
        e = (e > 0.f) ? e : 0.2f * e;
        m = fmaxf(m, e);
    }
#pragma unroll
    for (int o = 16; o; o >>= 1) m = fmaxf(m, __shfl_xor_sync(0xffffffffu, m, o));
    if (!isfinite(m)) m = 0.f;

    float sum = 0.f;
    for (int j = beg + lane; j < end; j += 32) {
        int s = d_csr_src[j];
        float e = d_as[s] + adn;
        e = (e > 0.f) ? e : 0.2f * e;
        sum += expf(e - m);
    }
#pragma unroll
    for (int o = 16; o; o >>= 1) sum += __shfl_xor_sync(0xffffffffu, sum, o);
    const float inv = 1.0f / (sum + 1e-16f);

    const float4* bc4 = (const float4*)b_conv;
    float4 a0 = bc4[lane];
    float4 a1 = bc4[lane + 32];
    float4 a2 = bc4[lane + 64];
    float4 a3 = bc4[lane + 96];
    for (int j = beg; j < end; j++) {
        int s = d_csr_src[j];
        float e = d_as[s] + adn;
        e = (e > 0.f) ? e : 0.2f * e;
        float alpha = expf(e - m) * inv;
        const float4* hr = (const float4*)(d_h + (size_t)s * HC);
        float4 v;
        v = hr[lane];      a0.x += alpha * v.x; a0.y += alpha * v.y; a0.z += alpha * v.z; a0.w += alpha * v.w;
        v = hr[lane + 32]; a1.x += alpha * v.x; a1.y += alpha * v.y; a1.z += alpha * v.z; a1.w += alpha * v.w;
        v = hr[lane + 64]; a2.x += alpha * v.x; a2.y += alpha * v.y; a2.z += alpha * v.z; a2.w += alpha * v.w;
        v = hr[lane + 96]; a3.x += alpha * v.x; a3.y += alpha * v.y; a3.z += alpha * v.z; a3.w += alpha * v.w;
    }
    float4* out4 = (float4*)(d_hconv + (size_t)n * HC);
    out4[lane] = a0; out4[lane + 32] = a1; out4[lane + 64] = a2; out4[lane + 96] = a3;

    const float4* wg4 = (const float4*)Wg;
    float gd = 0.f;
    float4 w;
    w = wg4[lane];      gd += a0.x * w.x + a0.y * w.y + a0.z * w.z + a0.w * w.w;
    w = wg4[lane + 32]; gd += a1.x * w.x + a1.y * w.y + a1.z * w.z + a1.w * w.w;
    w = wg4[lane + 64]; gd += a2.x * w.x + a2.y * w.y + a2.z * w.z + a2.w * w.w;
    w = wg4[lane + 96]; gd += a3.x * w.x + a3.y * w.y + a3.z * w.z + a3.w * w.w;
#pragma unroll
    for (int o = 16; o; o >>= 1) gd += __shfl_xor_sync(0xffffffffu, gd, o);
    if (lane == 0) d_gate[n] = gd + bg[0];
}

// ---------------- batch softmax (G=8) ----------------
__global__ void batch_max_kernel(const void* __restrict__ batch) {
    __shared__ unsigned sm[GG];
    if (threadIdx.x < GG) sm[threadIdx.x] = 0x007FFFFFu;
    __syncthreads();
    int is64 = d_bat64;
    for (int i = blockIdx.x * blockDim.x + threadIdx.x; i < NN; i += gridDim.x * blockDim.x) {
        int b = load_idx(batch, i, is64);
        atomicMax(&sm[b], fenc(d_gate[i]));
    }
    __syncthreads();
    if (threadIdx.x < GG) atomicMax(&d_gmax[threadIdx.x], sm[threadIdx.x]);
}

__global__ void batch_sum_kernel(const void* __restrict__ batch) {
    __shared__ float ss[GG];
    __shared__ float mm[GG];
    if (threadIdx.x < GG) {
        ss[threadIdx.x] = 0.f;
        float mv = fdec(d_gmax[threadIdx.x]);
        mm[threadIdx.x] = isfinite(mv) ? mv : 0.f;
    }
    __syncthreads();
    int is64 = d_bat64;
    for (int i = blockIdx.x * blockDim.x + threadIdx.x; i < NN; i += gridDim.x * blockDim.x) {
        int b = load_idx(batch, i, is64);
        atomicAdd(&ss[b], expf(d_gate[i] - mm[b]));
    }
    __syncthreads();
    if (threadIdx.x < GG) atomicAdd(&d_gsum[threadIdx.x], ss[threadIdx.x]);
}

__global__ void g_kernel(const void* __restrict__ batch, float* __restrict__ out,
                         int out_size) {
    int i = blockIdx.x * blockDim.x + threadIdx.x;
    if (i >= NN) return;
    int b = load_idx(batch, i, d_bat64);
    float mv = fdec(d_gmax[b]);
    if (!isfinite(mv)) mv = 0.f;
    float g = expf(d_gate[i] - mv) / (d_gsum[b] + 1e-16f);
    d_g[i] = g;
    if (out_size >= GG + NN) out[GG + i] = g;
}

// ---------------- pooled pre-GEMM ----------------
__global__ __launch_bounds__(128) void pool_P_kernel(const void* __restrict__ batch) {
    const int col = blockIdx.x * 128 + threadIdx.x;
    const int r0 = blockIdx.y * 128;
    const int rend = min(r0 + 128, NN);
    const int is64 = d_bat64;
    float acc = 0.f;
    int cur = load_idx(batch, r0, is64);
    for (int r = r0; r < rend; r++) {
        int b = load_idx(batch, r, is64);
        if (b != cur) {
            atomicAdd(&d_P[cur * HC + col], acc);
            acc = 0.f;
            cur = b;
        }
        acc += d_g[r] * d_hconv[(size_t)r * HC + col];
    }
    atomicAdd(&d_P[cur * HC + col], acc);
}

// ---------------- small [G,HC] @ [HC,HC] matmuls ----------------
__global__ void mm_small_kernel(const float* __restrict__ Bm, const float* __restrict__ bias,
                                int which) {
    int warp = (blockIdx.x * blockDim.x + threadIdx.x) >> 5;
    int lane = threadIdx.x & 31;
    if (warp >= GG * HC) return;
    int gi = warp >> 9;
    int c = warp & 511;
    const float* A = (which == 0) ? d_P : d_pooled;
    float s = 0.f;
    for (int k = lane; k < HC; k += 32) s += A[gi * HC + k] * Bm[(size_t)k * HC + c];
#pragma unroll
    for (int o = 16; o; o >>= 1) s += __shfl_xor_sync(0xffffffffu, s, o);
    if (lane == 0) {
        float v = s + bias[c];
        if (which == 1) v = fmaxf(v, 0.f);
        if (which == 0) d_pooled[gi * HC + c] = v;
        else            d_t1[gi * HC + c] = v;
    }
}

__global__ void out_kernel(const float* __restrict__ W2, const float* __restrict__ b2,
                           float* __restrict__ out) {
    int warp = threadIdx.x >> 5;
    int lane = threadIdx.x & 31;
    if (warp >= GG) return;
    float s = 0.f;
    for (int k = lane; k < HC; k += 32) s += d_t1[warp * HC + k] * W2[k];
#pragma unroll
    for (int o = 16; o; o >>= 1) s += __shfl_xor_sync(0xffffffffu, s, o);
    if (lane == 0) {
        float v = s + b2[0];
        out[warp] = 1.0f / (1.0f + expf(-v));
    }
}

// ---------------- launch ----------------
extern "C" void kernel_launch(void* const* d_in, const int* in_sizes, int n_in,
                              void* d_out, int out_size) {
    const float* x       = (const float*)d_in[0];
    const void*  ei      = d_in[1];
    const void*  bat     = d_in[2];
    const float* W       = (const float*)d_in[3];
    const float* att_src = (const float*)d_in[4];
    const float* att_dst = (const float*)d_in[5];
    const float* b_conv  = (const float*)d_in[6];
    const float* Wg      = (const float*)d_in[7];
    const float* bg      = (const float*)d_in[8];
    const float* Wn      = (const float*)d_in[9];
    const float* bn      = (const float*)d_in[10];
    const float* W1      = (const float*)d_in[11];
    const float* b1      = (const float*)d_in[12];
    const float* W2      = (const float*)d_in[13];
    const float* b2      = (const float*)d_in[14];
    float* out = (float*)d_out;

    static int smem_set = 0;
    if (!smem_set) {
        cudaFuncSetAttribute(gemm_mma_kernel, cudaFuncAttributeMaxDynamicSharedMemorySize, GEMM_SMEM);
        smem_set = 1;
    }

    detect_kernel<<<1, 32>>>(ei, bat);
    init_kernel<<<(NN + 255) / 256, 256>>>();

    // split + tensor-core GEMM: d_h = x @ W
    split_x_kernel<<<(NN * DD / 4 + 255) / 256, 256>>>(x);
    split_w_kernel<<<(DD * HC + 255) / 256, 256>>>(W);
    dim3 gg(HC / 128, (NN + 127) / 128);
    gemm_mma_kernel<<<gg, 256, GEMM_SMEM>>>();

    gemv_attn_kernel<<<(NN * 32 + 255) / 256, 256>>>(att_src, att_dst);

    count_deg_kernel<<<(EE + 255) / 256, 256>>>(ei);
    scan_kernel<<<1, 1024>>>();
    fill_self_kernel<<<(NN + 255) / 256, 256>>>();
    fill_edges_kernel<<<(EE + 255) / 256, 256>>>(ei);

    gather_kernel<<<(NN * 32 + 255) / 256, 256>>>(b_conv, Wg, bg);

    batch_max_kernel<<<200, 256>>>(bat);
    batch_sum_kernel<<<200, 256>>>(bat);
    g_kernel<<<(NN + 255) / 256, 256>>>(bat, out, out_size);

    dim3 pg(HC / 128, (NN + 127) / 128);
    pool_P_kernel<<<pg, 128>>>(bat);

    mm_small_kernel<<<(GG * HC * 32 + 255) / 256, 256>>>(Wn, bn, 0);
    mm_small_kernel<<<(GG * HC * 32 + 255) / 256, 256>>>(W1, b1, 1);
    out_kernel<<<1, 256>>>(W2, b2, out);
}